// round 3
// baseline (speedup 1.0000x reference)
#include <cuda_runtime.h>

#define LN 1000000
#define DN 16
#define WN 64
#define KN 8
#define TILE 2048
#define XCOLS 2112   /* TILE + 64 */
#define THREADS 256
#define RPT 8        /* outputs per thread */

__device__ __forceinline__ unsigned long long pk2(float lo, float hi) {
    unsigned long long r;
    asm("mov.b64 %0, {%1, %2};" : "=l"(r) : "f"(lo), "f"(hi));
    return r;
}
__device__ __forceinline__ void ffma2(unsigned long long &a, unsigned long long xv, unsigned long long pv) {
    asm("fma.rn.f32x2 %0, %1, %2, %0;" : "+l"(a) : "l"(xv), "l"(pv));
}

extern __shared__ unsigned char smem_raw[];

__global__ void __launch_bounds__(THREADS, 1)
fullscan_main(const float* __restrict__ x, const float* __restrict__ P,
              float* __restrict__ out) {
    unsigned long long* p2s = (unsigned long long*)smem_raw;   // 8192 * 8B = 64 KB, layout [k*1024 + d*64 + w]
    float* xs = (float*)(smem_raw + 65536);                    // 16 * 2112 * 4B = 132 KB

    const int tid = threadIdx.x;
    const long long base = (long long)blockIdx.x * TILE;
    const int gstart = (int)base - 31;

    // P duplicated into packed pairs (p, p) so inner loop does LDS.128 broadcasts
    #pragma unroll
    for (int i = 0; i < 8192 / THREADS; i++) {
        int idx = tid + i * THREADS;
        float p = P[idx];
        p2s[idx] = pk2(p, p);
    }
    // x tile with index clamping (edge blocks; interior values there get
    // overwritten by the boundary kernel anyway)
    for (int d = 0; d < DN; d++) {
        const float* xrow = x + (size_t)d * LN;
        float* row = xs + d * XCOLS;
        for (int j = tid; j < XCOLS; j += THREADS) {
            int g = gstart + j;
            g = g < 0 ? 0 : (g > LN - 1 ? LN - 1 : g);
            row[j] = xrow[g];
        }
    }
    __syncthreads();

    unsigned long long acc[KN][4];
    #pragma unroll
    for (int k = 0; k < KN; k++)
        #pragma unroll
        for (int p = 0; p < 4; p++) acc[k][p] = 0ull;

    const int toff = tid * RPT;

    #pragma unroll 1
    for (int d = 0; d < DN; d++) {
        const float* xr = xs + d * XCOLS + toff;
        const unsigned long long* pr = p2s + d * WN;

        float w0, w1, w2, w3, w4, w5, w6, w7;
        {
            float4 v = *(const float4*)(xr);
            float4 u = *(const float4*)(xr + 4);
            w0 = v.x; w1 = v.y; w2 = v.z; w3 = v.w;
            w4 = u.x; w5 = u.y; w6 = u.z; w7 = u.w;
        }

        #pragma unroll 1
        for (int w = 0; w < WN; w += 4) {
            float4 nv = *(const float4*)(xr + w + 8);
            // substep s, pair p uses x values (xr[w+s+2p], xr[w+s+2p+1])
            unsigned long long a0 = pk2(w0, w1), a1 = pk2(w2, w3);
            unsigned long long a2 = pk2(w4, w5), a3 = pk2(w6, w7);
            unsigned long long b0 = pk2(w1, w2), b1 = pk2(w3, w4);
            unsigned long long b2 = pk2(w5, w6), b3 = pk2(w7, nv.x);
            unsigned long long c3 = pk2(nv.x, nv.y);
            unsigned long long d3 = pk2(nv.y, nv.z);

            #pragma unroll
            for (int k = 0; k < KN; k++) {
                const unsigned long long* pp = pr + k * (DN * WN) + w;
                ulonglong2 p01 = *(const ulonglong2*)(pp);
                ulonglong2 p23 = *(const ulonglong2*)(pp + 2);
                // s = 0
                ffma2(acc[k][0], a0, p01.x); ffma2(acc[k][1], a1, p01.x);
                ffma2(acc[k][2], a2, p01.x); ffma2(acc[k][3], a3, p01.x);
                // s = 1
                ffma2(acc[k][0], b0, p01.y); ffma2(acc[k][1], b1, p01.y);
                ffma2(acc[k][2], b2, p01.y); ffma2(acc[k][3], b3, p01.y);
                // s = 2
                ffma2(acc[k][0], a1, p23.x); ffma2(acc[k][1], a2, p23.x);
                ffma2(acc[k][2], a3, p23.x); ffma2(acc[k][3], c3, p23.x);
                // s = 3
                ffma2(acc[k][0], b1, p23.y); ffma2(acc[k][1], b2, p23.y);
                ffma2(acc[k][2], b3, p23.y); ffma2(acc[k][3], d3, p23.y);
            }
            // slide window by 4
            w0 = w4; w1 = w5; w2 = w6; w3 = w7;
            w4 = nv.x; w5 = nv.y; w6 = nv.z; w7 = nv.w;
        }
    }

    long long i0 = base + toff;
    if (i0 < LN) {  // i0 is a multiple of 8 and LN % 8 == 0 -> full vector in range
        #pragma unroll
        for (int k = 0; k < KN; k++) {
            float* o = out + (size_t)k * LN + i0;
            float2 f0 = *(float2*)&acc[k][0];
            float2 f1 = *(float2*)&acc[k][1];
            float2 f2 = *(float2*)&acc[k][2];
            float2 f3 = *(float2*)&acc[k][3];
            *(float4*)(o)     = make_float4(f0.x, f0.y, f1.x, f1.y);
            *(float4*)(o + 4) = make_float4(f2.x, f2.y, f3.x, f3.y);
        }
    }
}

// Exact reference boundary semantics:
//  left[k,j]  = sum_{m=0}^{32+j}  sum_d x[d,m]       * P[k,d,m],  j in [0,31)  -> out[k*L + j]
//  right[k,j] = sum_{m=j+1}^{63}  sum_d x[d,L-64+m]  * P[k,d,m],  j in [0,32)  -> out[k*L + (L-32) + j]
__global__ void fullscan_boundary(const float* __restrict__ x, const float* __restrict__ P,
                                  float* __restrict__ out) {
    __shared__ float tl[KN][WN];
    __shared__ float tr[KN][WN];
    int tid = threadIdx.x;          // 512 threads
    int k = tid >> 6, m = tid & 63;
    float sl = 0.f, sr = 0.f;
    #pragma unroll
    for (int d = 0; d < DN; d++) {
        float p = P[k * (DN * WN) + d * WN + m];
        sl += x[(size_t)d * LN + m] * p;
        sr += x[(size_t)d * LN + (LN - WN) + m] * p;
    }
    tl[k][m] = sl; tr[k][m] = sr;
    __syncthreads();
    if (m < 31) {
        float s = 0.f;
        for (int mm = 0; mm <= 32 + m; mm++) s += tl[k][mm];
        out[(size_t)k * LN + m] = s;
    }
    if (m < 32) {
        float s = 0.f;
        for (int mm = m + 1; mm < WN; mm++) s += tr[k][mm];
        out[(size_t)k * LN + (LN - 32) + m] = s;
    }
}

extern "C" void kernel_launch(void* const* d_in, const int* in_sizes, int n_in,
                              void* d_out, int out_size) {
    const float* x = (const float*)d_in[0];
    const float* P = (const float*)d_in[1];
    float* out = (float*)d_out;

    const int smem_bytes = 65536 + DN * XCOLS * 4;   // 200704 B
    cudaFuncSetAttribute(fullscan_main, cudaFuncAttributeMaxDynamicSharedMemorySize, smem_bytes);

    const int nblocks = (LN + TILE - 1) / TILE;      // 489
    fullscan_main<<<nblocks, THREADS, smem_bytes>>>(x, P, out);
    fullscan_boundary<<<1, 512>>>(x, P, out);
}

// round 11
// speedup vs baseline: 2.6113x; 2.6113x over previous
#include <cuda_runtime.h>
#include <cuda_bf16.h>
#include <cstdint>

#define LN 1000000
#define DN 16
#define KN 8
#define WN 64
#define TOUT 176
#define NROWS 192               /* j rows: covers u+b <= 175+15 = 190 */
#define THREADS 256
#define XW 240                  /* TOUT + 64 */
#define XSTR 241
#define YSTR 196
#define NTILES ((LN + TOUT - 1) / TOUT)   /* 5682 */
#define GRID 152

/* smem byte offsets (1024-aligned bases for clean SW128) */
#define OFF_AH 0
#define OFF_AL 16384
#define OFF_BH 32768            /* 192*128 = 24576 B */
#define OFF_BL 57344
#define OFF_YS 81920            /* 128*196*4 = 100352 B; aliased as x staging */
#define SMEM_BYTES 182272

#define SW128(o) ((o) ^ (((o) >> 3) & 0x70))

static __device__ __nv_bfloat16 g_Ah[8192];   /* [m=128][col=64], col=16a+d, pre-swizzled */
static __device__ __nv_bfloat16 g_Al[8192];

__device__ __forceinline__ uint32_t smem_u32(const void* p) {
    uint32_t a;
    asm("{ .reg .u64 t; cvta.to.shared.u64 t, %1; cvt.u32.u64 %0, t; }" : "=r"(a) : "l"(p));
    return a;
}

__device__ __forceinline__ void ldsm_x4(uint32_t& r0, uint32_t& r1, uint32_t& r2, uint32_t& r3,
                                        uint32_t addr) {
    asm volatile("ldmatrix.sync.aligned.m8n8.x4.shared.b16 {%0,%1,%2,%3}, [%4];"
                 : "=r"(r0), "=r"(r1), "=r"(r2), "=r"(r3) : "r"(addr));
}
__device__ __forceinline__ void ldsm_x2(uint32_t& r0, uint32_t& r1, uint32_t addr) {
    asm volatile("ldmatrix.sync.aligned.m8n8.x2.shared.b16 {%0,%1}, [%2];"
                 : "=r"(r0), "=r"(r1) : "r"(addr));
}
__device__ __forceinline__ void mma16816(float* c, uint32_t a0, uint32_t a1, uint32_t a2,
                                         uint32_t a3, uint32_t b0, uint32_t b1) {
    asm volatile("mma.sync.aligned.m16n8k16.row.col.f32.bf16.bf16.f32 "
                 "{%0,%1,%2,%3}, {%4,%5,%6,%7}, {%8,%9}, {%0,%1,%2,%3};"
                 : "+f"(c[0]), "+f"(c[1]), "+f"(c[2]), "+f"(c[3])
                 : "r"(a0), "r"(a1), "r"(a2), "r"(a3), "r"(b0), "r"(b1));
}

/* A[(k,b)][col=16a+d] = P[k,d,16a+b], split into bf16 hi/lo, pre-swizzled */
__global__ void prep_A(const float* __restrict__ P) {
    int idx = blockIdx.x * blockDim.x + threadIdx.x;   /* 8192 */
    int m = idx >> 6, col = idx & 63;
    int k = m >> 4, b = m & 15, a = col >> 4, d = col & 15;
    float v = P[k * (DN * WN) + d * WN + 16 * a + b];
    __nv_bfloat16 h = __float2bfloat16(v);
    __nv_bfloat16 l = __float2bfloat16(v - __bfloat162float(h));
    uint32_t off = SW128((uint32_t)(m * 128 + col * 2));
    g_Ah[off >> 1] = h;
    g_Al[off >> 1] = l;
}

extern __shared__ unsigned char smem[];

__device__ __forceinline__ void prefetch_x(const float* __restrict__ x, int t, int tid,
                                           float* __restrict__ xr) {
    const int t0 = t * TOUT;
    #pragma unroll
    for (int j = 0; j < 15; j++) {
        int i = tid + j * THREADS;            /* 3840 = 15*256 = 16*240 */
        int d = i / XW, c = i - d * XW;
        int g = t0 - 31 + c;
        g = g < 0 ? 0 : (g > LN - 1 ? LN - 1 : g);
        xr[j] = __ldg(x + (size_t)d * LN + g);
    }
}

__global__ void __launch_bounds__(THREADS, 1)
fullscan_mma(const float* __restrict__ x, float* __restrict__ out) {
    const int tid = threadIdx.x;
    const int wid = tid >> 5;
    const int lid = tid & 31;
    const uint32_t sbase = smem_u32(smem);

    /* copy pre-swizzled A hi/lo into smem (32 KB) */
    {
        const uint4* gh = (const uint4*)g_Ah;
        const uint4* gl = (const uint4*)g_Al;
        uint4* sh = (uint4*)(smem + OFF_AH);
        uint4* sl = (uint4*)(smem + OFF_AL);
        #pragma unroll
        for (int i = 0; i < 4; i++) { sh[tid + i * THREADS] = gh[tid + i * THREADS]; }
        #pragma unroll
        for (int i = 0; i < 4; i++) { sl[tid + i * THREADS] = gl[tid + i * THREADS]; }
    }

    float* ys = (float*)(smem + OFF_YS);
    float* xs = (float*)(smem + OFF_YS);   /* staging aliases ys space */

    /* per-lane fragment address components (PTX ISA ldmatrix lane->address map) */
    const int arow = lid & 15;             /* A: row within m-tile */
    const int acol8 = (lid >> 4) << 3;     /* A: k-half (0 or 8) */
    const int bl16 = lid & 15;
    const int brow = bl16 & 7;             /* B: row within n-tile */
    const int bcol8 = (bl16 >> 3) << 3;    /* B: k-half (0 or 8) */
    const int n0w = wid * 24;              /* warp's 24-col N slice */

    float xr[15];
    prefetch_x(x, blockIdx.x, tid, xr);

    for (int t = blockIdx.x; t < NTILES; t += GRID) {
        const int t0 = t * TOUT;

        /* stage x tile from prefetched regs: xs[d][c], c in [0,240) */
        #pragma unroll
        for (int j = 0; j < 15; j++) {
            int i = tid + j * THREADS;
            int d = i / XW, c = i - d * XW;
            xs[d * XSTR + c] = xr[j];
        }
        __syncthreads();

        /* build B hi/lo: B[j][col=16a+d] = xs[d][j+16a]; 8 cols -> one STS.128 */
        for (int i = tid; i < NROWS * 8; i += THREADS) {
            int j = i >> 3, g = i & 7;
            int a = g >> 1, d0 = (g & 1) * 8;
            const float* xp = xs + d0 * XSTR + (j + 16 * a);
            uint32_t hv[4], lv[4];
            #pragma unroll
            for (int s = 0; s < 4; s++) {
                float v0 = xp[(2 * s) * XSTR];
                float v1 = xp[(2 * s + 1) * XSTR];
                __nv_bfloat16 h0 = __float2bfloat16(v0);
                __nv_bfloat16 h1 = __float2bfloat16(v1);
                __nv_bfloat16 l0 = __float2bfloat16(v0 - __bfloat162float(h0));
                __nv_bfloat16 l1 = __float2bfloat16(v1 - __bfloat162float(h1));
                hv[s] = (uint32_t)__bfloat16_as_ushort(h0) | ((uint32_t)__bfloat16_as_ushort(h1) << 16);
                lv[s] = (uint32_t)__bfloat16_as_ushort(l0) | ((uint32_t)__bfloat16_as_ushort(l1) << 16);
            }
            uint32_t off = SW128((uint32_t)(j * 128 + g * 16));
            *(uint4*)(smem + OFF_BH + off) = make_uint4(hv[0], hv[1], hv[2], hv[3]);
            *(uint4*)(smem + OFF_BL + off) = make_uint4(lv[0], lv[1], lv[2], lv[3]);
        }
        __syncthreads();

        /* prefetch next tile's x (LDG latency hides under the MMA loop) */
        {
            int tn = t + GRID;
            prefetch_x(x, tn < NTILES ? tn : 0, tid, xr);
        }

        /* warp GEMM: Y'[0:128][n0w:n0w+24], 3 bf16-split passes */
        float acc[8][3][4];
        #pragma unroll
        for (int mt = 0; mt < 8; mt++)
            #pragma unroll
            for (int nt = 0; nt < 3; nt++)
                #pragma unroll
                for (int r = 0; r < 4; r++) acc[mt][nt][r] = 0.f;

        #pragma unroll 1
        for (int split = 0; split < 3; split++) {
            const uint32_t aBase = sbase + ((split == 2) ? OFF_AL : OFF_AH);
            const uint32_t bBase = sbase + ((split == 1) ? OFF_BL : OFF_BH);
            #pragma unroll
            for (int kc = 0; kc < 4; kc++) {
                const int k0 = kc * 16;
                uint32_t b0[3], b1[3];
                #pragma unroll
                for (int nt = 0; nt < 3; nt++) {
                    uint32_t off = (uint32_t)((n0w + nt * 8 + brow) * 128 + (k0 + bcol8) * 2);
                    ldsm_x2(b0[nt], b1[nt], bBase + SW128(off));
                }
                #pragma unroll
                for (int mt = 0; mt < 8; mt++) {
                    uint32_t a0, a1, a2, a3;
                    uint32_t off = (uint32_t)((mt * 16 + arow) * 128 + (k0 + acol8) * 2);
                    ldsm_x4(a0, a1, a2, a3, aBase + SW128(off));
                    #pragma unroll
                    for (int nt = 0; nt < 3; nt++)
                        mma16816(acc[mt][nt], a0, a1, a2, a3, b0[nt], b1[nt]);
                }
            }
        }

        __syncthreads();   /* B consumed; ys region (aliases xs) free to write */

        /* epilogue: fragments -> ys[m][j] */
        {
            const int quad = lid >> 2, ql = lid & 3;
            #pragma unroll
            for (int mt = 0; mt < 8; mt++) {
                #pragma unroll
                for (int nt = 0; nt < 3; nt++) {
                    int r0 = mt * 16 + quad;
                    int c0 = n0w + nt * 8 + ql * 2;
                    *(float2*)(ys + r0 * YSTR + c0)       = make_float2(acc[mt][nt][0], acc[mt][nt][1]);
                    *(float2*)(ys + (r0 + 8) * YSTR + c0) = make_float2(acc[mt][nt][2], acc[mt][nt][3]);
                }
            }
        }
        __syncthreads();

        /* diagonal b-sum: y[k, t0+u] = sum_b ys[k*16+b][u+b] */
        for (int o = tid; o < KN * TOUT; o += THREADS) {
            int k = o / TOUT, u = o - k * TOUT;
            if (t0 + u < LN) {
                const float* yb = ys + (k * 16) * YSTR + u;
                float s = 0.f;
                #pragma unroll
                for (int b = 0; b < 16; b++) s += yb[b * YSTR + b];
                out[(size_t)k * LN + t0 + u] = s;
            }
        }
        __syncthreads();
    }
}

/* exact reference boundary semantics (overwrites first 31 / last 32 cols) */
__global__ void fullscan_boundary(const float* __restrict__ x, const float* __restrict__ P,
                                  float* __restrict__ out) {
    __shared__ float tl[KN][WN];
    __shared__ float tr[KN][WN];
    int tid = threadIdx.x;          /* 512 threads */
    int k = tid >> 6, m = tid & 63;
    float sl = 0.f, sr = 0.f;
    #pragma unroll
    for (int d = 0; d < DN; d++) {
        float p = P[k * (DN * WN) + d * WN + m];
        sl += x[(size_t)d * LN + m] * p;
        sr += x[(size_t)d * LN + (LN - WN) + m] * p;
    }
    tl[k][m] = sl; tr[k][m] = sr;
    __syncthreads();
    if (m < 31) {
        float s = 0.f;
        for (int mm = 0; mm <= 32 + m; mm++) s += tl[k][mm];
        out[(size_t)k * LN + m] = s;
    }
    if (m < 32) {
        float s = 0.f;
        for (int mm = m + 1; mm < WN; mm++) s += tr[k][mm];
        out[(size_t)k * LN + (LN - 32) + m] = s;
    }
}

extern "C" void kernel_launch(void* const* d_in, const int* in_sizes, int n_in,
                              void* d_out, int out_size) {
    const float* x = (const float*)d_in[0];
    const float* P = (const float*)d_in[1];
    float* out = (float*)d_out;

    cudaFuncSetAttribute(fullscan_mma, cudaFuncAttributeMaxDynamicSharedMemorySize, SMEM_BYTES);

    prep_A<<<32, 256>>>(P);
    fullscan_mma<<<GRID, THREADS, SMEM_BYTES>>>(x, out);
    fullscan_boundary<<<1, 512>>>(x, P, out);
}